// round 2
// baseline (speedup 1.0000x reference)
#include <cuda_runtime.h>
#include <cuda_fp16.h>
#include <cstdint>

// ---------------- problem dims ----------------
#define BATCH_SZ 16384
#define IN_F     2048
#define OUT_F    2048
#define NSEG     6
#define KTOT     (IN_F * NSEG)   // 12288

// ---------------- GEMM tiling ----------------
#define BM 128
#define BN 256
#define BK 64
#define STAGES 3
#define KITERS (KTOT / BK)       // 192

#define LDS_STRIDE 72                        // halves per smem row (64 data + 8 pad)
#define A_STG_HALVES (BM * LDS_STRIDE)       // 9216
#define B_STG_HALVES (BN * LDS_STRIDE)       // 18432
#define SMEM_BYTES ((STAGES * (A_STG_HALVES + B_STG_HALVES)) * 2)  // 165888

// ---------------- scratch (device globals; no alloc allowed) ----------------
static __device__ __align__(1024) __half g_Apack[(size_t)BATCH_SZ * KTOT]; // 402 MB
static __device__ __align__(1024) __half g_Wpack[(size_t)OUT_F * KTOT];   // 50 MB

// ---------------- helpers ----------------
__device__ __forceinline__ uint32_t smem_u32(const void* p) {
    uint32_t a;
    asm("{ .reg .u64 t; cvta.to.shared.u64 t, %1; cvt.u32.u64 %0, t; }" : "=r"(a) : "l"(p));
    return a;
}
__device__ __forceinline__ void cp16(uint32_t saddr, const void* g) {
    asm volatile("cp.async.cg.shared.global [%0], [%1], 16;" :: "r"(saddr), "l"(g) : "memory");
}
__device__ __forceinline__ void cp_commit() {
    asm volatile("cp.async.commit_group;" ::: "memory");
}
template <int N>
__device__ __forceinline__ void cp_wait() {
    asm volatile("cp.async.wait_group %0;" :: "n"(N) : "memory");
}
__device__ __forceinline__ void ldsm4(uint32_t* r, uint32_t addr) {
    asm volatile("ldmatrix.sync.aligned.m8n8.x4.shared.b16 {%0,%1,%2,%3}, [%4];"
                 : "=r"(r[0]), "=r"(r[1]), "=r"(r[2]), "=r"(r[3]) : "r"(addr));
}
__device__ __forceinline__ void mma16816(float* c, const uint32_t* a, uint32_t b0, uint32_t b1) {
    asm volatile(
        "mma.sync.aligned.m16n8k16.row.col.f32.f16.f16.f32 "
        "{%0,%1,%2,%3}, {%4,%5,%6,%7}, {%8,%9}, {%0,%1,%2,%3};"
        : "+f"(c[0]), "+f"(c[1]), "+f"(c[2]), "+f"(c[3])
        : "r"(a[0]), "r"(a[1]), "r"(a[2]), "r"(a[3]), "r"(b0), "r"(b1));
}

// ---------------- kernel 1: A expansion (silu + RBF basis -> fp16) ----------------
__global__ void __launch_bounds__(256) expand_kernel(const float* __restrict__ x,
                                                     __half* __restrict__ A) {
    int idx = blockIdx.x * blockDim.x + threadIdx.x;   // one thread per 4 input elems
    int b = idx >> 9;                                   // 512 quads per row
    int i = (idx & 511) << 2;
    float4 xv = *reinterpret_cast<const float4*>(x + (size_t)b * IN_F + i);
    float xs[4] = {xv.x, xv.y, xv.z, xv.w};
    __half2 seg[NSEG][2];
#pragma unroll
    for (int p = 0; p < 2; p++) {
        float a0 = xs[2 * p], a1 = xs[2 * p + 1];
        float s0 = a0 / (1.f + __expf(-a0));
        float s1 = a1 / (1.f + __expf(-a1));
        seg[0][p] = __floats2half2_rn(s0, s1);
#pragma unroll
        for (int g = 0; g < 5; g++) {
            float gg = -1.f + 0.5f * (float)g;
            float d0 = a0 - gg, d1 = a1 - gg;
            seg[g + 1][p] = __floats2half2_rn(__expf(-5.f * d0 * d0), __expf(-5.f * d1 * d1));
        }
    }
    __half* Ab = A + (size_t)b * KTOT + i;
#pragma unroll
    for (int s = 0; s < NSEG; s++) {
        *reinterpret_cast<__half2*>(Ab + s * IN_F)     = seg[s][0];
        *reinterpret_cast<__half2*>(Ab + s * IN_F + 2) = seg[s][1];
    }
}

// ---------------- kernel 2: weight pack -> fp16 [OUT_F, KTOT] ----------------
__global__ void __launch_bounds__(256) wpack_kernel(const float* __restrict__ bw,
                                                    const float* __restrict__ sw,
                                                    __half* __restrict__ W) {
    int idx = blockIdx.x * blockDim.x + threadIdx.x;   // OUT_F*IN_F threads
    int o = idx >> 11, i = idx & 2047;
    __half* Wo = W + (size_t)o * KTOT + i;
    Wo[0] = __float2half_rn(bw[idx]);
    const float* sp = sw + (size_t)idx * 5;
#pragma unroll
    for (int g = 0; g < 5; g++) Wo[(size_t)(g + 1) * IN_F] = __float2half_rn(sp[g]);
}

// ---------------- kernel 3: mma.sync fp16 GEMM (cp.async pipelined) ----------------
__global__ void __launch_bounds__(256, 1)
gemm_kernel(const __half* __restrict__ A, const __half* __restrict__ B,
            float* __restrict__ out) {
    extern __shared__ char smem_raw[];
    const uint32_t smemA = smem_u32(smem_raw);
    const uint32_t smemB = smemA + STAGES * A_STG_HALVES * 2;

    const int tid = threadIdx.x;
    const int w = tid >> 5, l = tid & 31;
    const int wm = (w >> 2) * 64;           // warp row offset in CTA tile
    const int wn = (w & 3) * 64;            // warp col offset in CTA tile
    const int ntile = blockIdx.x, mtile = blockIdx.y;

    const __half* gA = A + (size_t)(mtile * BM) * KTOT;
    const __half* gB = B + (size_t)(ntile * BN) * KTOT;

    // per-thread cp.async coordinates (A: 4 chunks, B: 8 chunks of 16B)
    // idx -> row = idx/8, chunk = idx%8 (chunk = 8 halves)
    // ldmatrix lane base offsets (halves)
    const uint32_t a_lane = (uint32_t)((wm + (l & 15)) * LDS_STRIDE + (l >> 4) * 8);
    const uint32_t b_lane = (uint32_t)((wn + (l & 15)) * LDS_STRIDE + (l >> 4) * 8);

    float acc[4][8][4];
#pragma unroll
    for (int mi = 0; mi < 4; mi++)
#pragma unroll
        for (int j = 0; j < 8; j++)
#pragma unroll
            for (int q = 0; q < 4; q++) acc[mi][j][q] = 0.f;

    auto load_stage = [&](int slot, int kc) {
#pragma unroll
        for (int r = 0; r < 4; r++) {
            int idx = tid + r * 256;
            int row = idx >> 3, ch = idx & 7;
            uint32_t sa = smemA + (uint32_t)(slot * A_STG_HALVES + row * LDS_STRIDE + ch * 8) * 2;
            cp16(sa, gA + (size_t)row * KTOT + kc * BK + ch * 8);
        }
#pragma unroll
        for (int r = 0; r < 8; r++) {
            int idx = tid + r * 256;
            int row = idx >> 3, ch = idx & 7;
            uint32_t sb = smemB + (uint32_t)(slot * B_STG_HALVES + row * LDS_STRIDE + ch * 8) * 2;
            cp16(sb, gB + (size_t)row * KTOT + kc * BK + ch * 8);
        }
    };

    // prologue: prefetch 2 stages
    load_stage(0, 0); cp_commit();
    load_stage(1, 1); cp_commit();

    for (int kc = 0; kc < KITERS; kc++) {
        cp_wait<1>();            // stage kc resident
        __syncthreads();         // all warps done with slot we are about to overwrite

        int nk = kc + 2;
        if (nk < KITERS) load_stage(nk % STAGES, nk);
        cp_commit();             // empty group at tail keeps wait_group accounting exact

        const int slot = kc % STAGES;
        const uint32_t aB = smemA + (uint32_t)(slot * A_STG_HALVES) * 2 + a_lane * 2;
        const uint32_t bB = smemB + (uint32_t)(slot * B_STG_HALVES) * 2 + b_lane * 2;

#pragma unroll
        for (int ks = 0; ks < 4; ks++) {
            uint32_t af[4][4], bf[4][4];
#pragma unroll
            for (int mi = 0; mi < 4; mi++)
                ldsm4(af[mi], aB + (uint32_t)(mi * 16 * LDS_STRIDE + ks * 16) * 2);
#pragma unroll
            for (int ni = 0; ni < 4; ni++)
                ldsm4(bf[ni], bB + (uint32_t)(ni * 16 * LDS_STRIDE + ks * 16) * 2);
#pragma unroll
            for (int mi = 0; mi < 4; mi++) {
#pragma unroll
                for (int ni = 0; ni < 4; ni++) {
                    mma16816(acc[mi][2 * ni],     af[mi], bf[ni][0], bf[ni][2]);
                    mma16816(acc[mi][2 * ni + 1], af[mi], bf[ni][1], bf[ni][3]);
                }
            }
        }
    }

    // epilogue: regs -> gmem
#pragma unroll
    for (int mi = 0; mi < 4; mi++) {
        int row = mtile * BM + wm + mi * 16 + (l >> 2);
        float* orow = out + (size_t)row * OUT_F + ntile * BN + wn + (l & 3) * 2;
#pragma unroll
        for (int j = 0; j < 8; j++) {
            *reinterpret_cast<float2*>(orow + j * 8) =
                make_float2(acc[mi][j][0], acc[mi][j][1]);
            *reinterpret_cast<float2*>(orow + j * 8 + 8 * OUT_F) =
                make_float2(acc[mi][j][2], acc[mi][j][3]);
        }
    }
}

// ---------------- host launch ----------------
extern "C" void kernel_launch(void* const* d_in, const int* in_sizes, int n_in,
                              void* d_out, int out_size) {
    (void)in_sizes; (void)n_in; (void)out_size;
    const float* x  = (const float*)d_in[0];
    const float* bw = (const float*)d_in[1];
    const float* sw = (const float*)d_in[2];
    float* out = (float*)d_out;

    void *aptr = nullptr, *wptr = nullptr;
    cudaGetSymbolAddress(&aptr, g_Apack);
    cudaGetSymbolAddress(&wptr, g_Wpack);

    expand_kernel<<<(BATCH_SZ * IN_F / 4) / 256, 256>>>(x, (__half*)aptr);
    wpack_kernel<<<(OUT_F * IN_F) / 256, 256>>>(bw, sw, (__half*)wptr);

    cudaFuncSetAttribute(gemm_kernel, cudaFuncAttributeMaxDynamicSharedMemorySize, SMEM_BYTES);
    gemm_kernel<<<dim3(OUT_F / BN, BATCH_SZ / BM), 256, SMEM_BYTES>>>(
        (const __half*)aptr, (const __half*)wptr, out);
}

// round 4
// speedup vs baseline: 1.0229x; 1.0229x over previous
#include <cuda_runtime.h>
#include <cuda_fp16.h>
#include <cstdint>

// ---------------- problem dims ----------------
#define BATCH_SZ 16384
#define IN_F     2048
#define OUT_F    2048
#define NSEG     6
#define KTOT     (IN_F * NSEG)   // 12288

// ---------------- GEMM tiling ----------------
#define BM 128
#define BN 256
#define BK 64
#define STAGES 4
#define KITERS (KTOT / BK)       // 192

#define LDS_STRIDE 72                        // halves per smem row (64 data + 8 pad)
#define A_STG_HALVES (BM * LDS_STRIDE)       // 9216
#define B_STG_HALVES (BN * LDS_STRIDE)       // 18432
#define SMEM_BYTES ((STAGES * (A_STG_HALVES + B_STG_HALVES)) * 2)  // 221184

// ---------------- scratch (device globals; no alloc allowed) ----------------
static __device__ __align__(1024) __half g_Apack[(size_t)BATCH_SZ * KTOT]; // 402 MB
static __device__ __align__(1024) __half g_Wpack[(size_t)OUT_F * KTOT];   // 50 MB

// ---------------- helpers ----------------
__device__ __forceinline__ uint32_t smem_u32(const void* p) {
    uint32_t a;
    asm("{ .reg .u64 t; cvta.to.shared.u64 t, %1; cvt.u32.u64 %0, t; }" : "=r"(a) : "l"(p));
    return a;
}
__device__ __forceinline__ void cp16(uint32_t saddr, const void* g) {
    asm volatile("cp.async.cg.shared.global [%0], [%1], 16;" :: "r"(saddr), "l"(g) : "memory");
}
__device__ __forceinline__ void cp_commit() {
    asm volatile("cp.async.commit_group;" ::: "memory");
}
template <int N>
__device__ __forceinline__ void cp_wait() {
    asm volatile("cp.async.wait_group %0;" :: "n"(N) : "memory");
}
__device__ __forceinline__ void ldsm4(uint32_t* r, uint32_t addr) {
    asm volatile("ldmatrix.sync.aligned.m8n8.x4.shared.b16 {%0,%1,%2,%3}, [%4];"
                 : "=r"(r[0]), "=r"(r[1]), "=r"(r[2]), "=r"(r[3]) : "r"(addr));
}
__device__ __forceinline__ void mma16816(float* c, const uint32_t* a, uint32_t b0, uint32_t b1) {
    asm volatile(
        "mma.sync.aligned.m16n8k16.row.col.f32.f16.f16.f32 "
        "{%0,%1,%2,%3}, {%4,%5,%6,%7}, {%8,%9}, {%0,%1,%2,%3};"
        : "+f"(c[0]), "+f"(c[1]), "+f"(c[2]), "+f"(c[3])
        : "r"(a[0]), "r"(a[1]), "r"(a[2]), "r"(a[3]), "r"(b0), "r"(b1));
}

// ---------------- kernel 1: A expansion (silu + RBF basis -> fp16) ----------------
__global__ void __launch_bounds__(256) expand_kernel(const float* __restrict__ x,
                                                     __half* __restrict__ A) {
    int idx = blockIdx.x * blockDim.x + threadIdx.x;   // one thread per 4 input elems
    int b = idx >> 9;                                   // 512 quads per row
    int i = (idx & 511) << 2;
    float4 xv = *reinterpret_cast<const float4*>(x + (size_t)b * IN_F + i);
    float xs[4] = {xv.x, xv.y, xv.z, xv.w};
    __half2 seg[NSEG][2];
#pragma unroll
    for (int p = 0; p < 2; p++) {
        float a0 = xs[2 * p], a1 = xs[2 * p + 1];
        float s0 = a0 / (1.f + __expf(-a0));
        float s1 = a1 / (1.f + __expf(-a1));
        seg[0][p] = __floats2half2_rn(s0, s1);
#pragma unroll
        for (int g = 0; g < 5; g++) {
            float gg = -1.f + 0.5f * (float)g;
            float d0 = a0 - gg, d1 = a1 - gg;
            seg[g + 1][p] = __floats2half2_rn(__expf(-5.f * d0 * d0), __expf(-5.f * d1 * d1));
        }
    }
    __half* Ab = A + (size_t)b * KTOT + i;
#pragma unroll
    for (int s = 0; s < NSEG; s++) {
        *reinterpret_cast<__half2*>(Ab + s * IN_F)     = seg[s][0];
        *reinterpret_cast<__half2*>(Ab + s * IN_F + 2) = seg[s][1];
    }
}

// ---------------- kernel 2: weight pack -> fp16 [OUT_F, KTOT] ----------------
__global__ void __launch_bounds__(256) wpack_kernel(const float* __restrict__ bw,
                                                    const float* __restrict__ sw,
                                                    __half* __restrict__ W) {
    int idx = blockIdx.x * blockDim.x + threadIdx.x;   // OUT_F*IN_F threads
    int o = idx >> 11, i = idx & 2047;
    __half* Wo = W + (size_t)o * KTOT + i;
    Wo[0] = __float2half_rn(bw[idx]);
    const float* sp = sw + (size_t)idx * 5;
#pragma unroll
    for (int g = 0; g < 5; g++) Wo[(size_t)(g + 1) * IN_F] = __float2half_rn(sp[g]);
}

// ---------------- fragment helpers ----------------
__device__ __forceinline__ void load_afrags(uint32_t (*af)[4], uint32_t aB, int ks) {
#pragma unroll
    for (int mi = 0; mi < 4; mi++)
        ldsm4(af[mi], aB + (uint32_t)(mi * 16 * LDS_STRIDE + ks * 16) * 2);
}
__device__ __forceinline__ void load_bfrags(uint32_t (*bf)[4], uint32_t bB, int ks) {
#pragma unroll
    for (int ni = 0; ni < 4; ni++)
        ldsm4(bf[ni], bB + (uint32_t)(ni * 16 * LDS_STRIDE + ks * 16) * 2);
}
__device__ __forceinline__ void mma_step(float (*acc)[8][4], uint32_t (*af)[4],
                                         uint32_t (*bf)[4]) {
#pragma unroll
    for (int mi = 0; mi < 4; mi++) {
#pragma unroll
        for (int ni = 0; ni < 4; ni++) {
            mma16816(acc[mi][2 * ni],     af[mi], bf[ni][0], bf[ni][2]);
            mma16816(acc[mi][2 * ni + 1], af[mi], bf[ni][1], bf[ni][3]);
        }
    }
}

// ---------------- kernel 3: mma.sync fp16 GEMM (4-stage cp.async, reg dbuf) ---------
__global__ void __launch_bounds__(256, 1)
gemm_kernel(const __half* __restrict__ A, const __half* __restrict__ B,
            float* __restrict__ out) {
    extern __shared__ char smem_raw[];
    const uint32_t smemA = smem_u32(smem_raw);
    const uint32_t smemB = smemA + STAGES * A_STG_HALVES * 2;

    const int tid = threadIdx.x;
    const int w = tid >> 5, l = tid & 31;
    const int wm = (w >> 2) * 64;           // warp row offset in CTA tile
    const int wn = (w & 3) * 64;            // warp col offset in CTA tile
    const int ntile = blockIdx.x, mtile = blockIdx.y;

    const __half* gA = A + (size_t)(mtile * BM) * KTOT;
    const __half* gB = B + (size_t)(ntile * BN) * KTOT;

    const uint32_t a_lane = (uint32_t)((wm + (l & 15)) * LDS_STRIDE + (l >> 4) * 8);
    const uint32_t b_lane = (uint32_t)((wn + (l & 15)) * LDS_STRIDE + (l >> 4) * 8);

    float acc[4][8][4];
#pragma unroll
    for (int mi = 0; mi < 4; mi++)
#pragma unroll
        for (int j = 0; j < 8; j++)
#pragma unroll
            for (int q = 0; q < 4; q++) acc[mi][j][q] = 0.f;

    auto load_stage = [&](int slot, int kc) {
#pragma unroll
        for (int r = 0; r < 4; r++) {
            int idx = tid + r * 256;
            int row = idx >> 3, ch = idx & 7;
            uint32_t sa = smemA + (uint32_t)(slot * A_STG_HALVES + row * LDS_STRIDE + ch * 8) * 2;
            cp16(sa, gA + (size_t)row * KTOT + kc * BK + ch * 8);
        }
#pragma unroll
        for (int r = 0; r < 8; r++) {
            int idx = tid + r * 256;
            int row = idx >> 3, ch = idx & 7;
            uint32_t sb = smemB + (uint32_t)(slot * B_STG_HALVES + row * LDS_STRIDE + ch * 8) * 2;
            cp16(sb, gB + (size_t)row * KTOT + kc * BK + ch * 8);
        }
    };

    // prologue: prefetch 3 stages
    load_stage(0, 0); cp_commit();
    load_stage(1, 1); cp_commit();
    load_stage(2, 2); cp_commit();

    uint32_t af[2][4][4], bf[2][4][4];

    for (int kc = 0; kc < KITERS; kc++) {
        const int slot = kc & (STAGES - 1);
        const uint32_t aB = smemA + (uint32_t)(slot * A_STG_HALVES) * 2 + a_lane * 2;
        const uint32_t bB = smemB + (uint32_t)(slot * B_STG_HALVES) * 2 + b_lane * 2;

        cp_wait<2>();                 // my own stage-kc copies complete
        __syncthreads();              // everyone's stage-kc copies complete + visible;
                                      // also: all warps done reading slot (kc+3)&3

        int nk = kc + 3;
        if (nk < KITERS) load_stage(nk & (STAGES - 1), nk);
        cp_commit();                  // exactly one group per iteration

        // ks=0 fragment prefetch (safe: after wait+barrier)
        load_afrags(af[0], aB, 0);
        load_bfrags(bf[0], bB, 0);

#pragma unroll
        for (int ks = 0; ks < 4; ks++) {
            const int cur = ks & 1, nxt = cur ^ 1;
            if (ks < 3) {
                load_afrags(af[nxt], aB, ks + 1);
                load_bfrags(bf[nxt], bB, ks + 1);
            }
            mma_step(acc, af[cur], bf[cur]);
        }
    }

    // epilogue: regs -> gmem
#pragma unroll
    for (int mi = 0; mi < 4; mi++) {
        int row = mtile * BM + wm + mi * 16 + (l >> 2);
        float* orow = out + (size_t)row * OUT_F + ntile * BN + wn + (l & 3) * 2;
#pragma unroll
        for (int j = 0; j < 8; j++) {
            *reinterpret_cast<float2*>(orow + j * 8) =
                make_float2(acc[mi][j][0], acc[mi][j][1]);
            *reinterpret_cast<float2*>(orow + j * 8 + 8 * OUT_F) =
                make_float2(acc[mi][j][2], acc[mi][j][3]);
        }
    }
}

// ---------------- host launch ----------------
extern "C" void kernel_launch(void* const* d_in, const int* in_sizes, int n_in,
                              void* d_out, int out_size) {
    (void)in_sizes; (void)n_in; (void)out_size;
    const float* x  = (const float*)d_in[0];
    const float* bw = (const float*)d_in[1];
    const float* sw = (const float*)d_in[2];
    float* out = (float*)d_out;

    void *aptr = nullptr, *wptr = nullptr;
    cudaGetSymbolAddress(&aptr, g_Apack);
    cudaGetSymbolAddress(&wptr, g_Wpack);

    expand_kernel<<<(BATCH_SZ * IN_F / 4) / 256, 256>>>(x, (__half*)aptr);
    wpack_kernel<<<(OUT_F * IN_F) / 256, 256>>>(bw, sw, (__half*)wptr);

    cudaFuncSetAttribute(gemm_kernel, cudaFuncAttributeMaxDynamicSharedMemorySize, SMEM_BYTES);
    gemm_kernel<<<dim3(OUT_F / BN, BATCH_SZ / BM), 256, SMEM_BYTES>>>(
        (const __half*)aptr, (const __half*)wptr, out);
}